// round 3
// baseline (speedup 1.0000x reference)
#include <cuda_runtime.h>
#include <cuda_bf16.h>
#include <mma.h>
#include <cstdint>
#include <cstddef>

using namespace nvcuda;

// ---------------- problem constants ----------------
#define BB  2048
#define IN  4096
#define ED  8192
#define PW  2048
#define OUTD 256
#define CLN 16
#define NK  32
#define CAP 512

// ---------------- device scratch (allowed: __device__ globals) ----------------
__device__ __nv_bfloat16 g_W1h[(size_t)IN * IN];
__device__ __nv_bfloat16 g_W2h[(size_t)ED * IN];
__device__ __nv_bfloat16 g_W3h[(size_t)PW * ED];
__device__ __nv_bfloat16 g_W4h[(size_t)OUTD * PW];
__device__ __nv_bfloat16 g_W5h[(size_t)OUTD * OUTD];
__device__ __nv_bfloat16 g_Xgh[(size_t)BB * IN];
__device__ float         g_A1 [(size_t)BB * IN];
__device__ __nv_bfloat16 g_A1h[(size_t)BB * IN];
__device__ float         g_A2 [(size_t)BB * ED];
__device__ __nv_bfloat16 g_A2h[(size_t)BB * ED];
__device__ float         g_A3 [(size_t)BB * PW];
__device__ __nv_bfloat16 g_A3h[(size_t)BB * PW];
__device__ float         g_A4 [(size_t)BB * OUTD];
__device__ __nv_bfloat16 g_A4h[(size_t)BB * OUTD];
__device__ float         g_A5 [(size_t)BB * OUTD];
__device__ float         g_kept[4][BB * NK];
__device__ int           g_nzi[4][NK * CAP];
__device__ float         g_nzv[4][NK * CAP];
__device__ int           g_nzc[4][NK];

// ---------------- helpers ----------------
__device__ __forceinline__ float sigf(float x) { return 1.0f / (1.0f + __expf(-x)); }

__device__ __forceinline__ void cp16(void* s, const void* g) {
    unsigned sa = (unsigned)__cvta_generic_to_shared(s);
    asm volatile("cp.async.cg.shared.global [%0], [%1], 16;\n" :: "r"(sa), "l"(g) : "memory");
}
__device__ __forceinline__ void cp_commit() { asm volatile("cp.async.commit_group;\n" ::: "memory"); }
__device__ __forceinline__ void cp_wait0()  { asm volatile("cp.async.wait_group 0;\n" ::: "memory"); }

// ---------------- premask / convert ----------------
__global__ void premask_k(const float4* __restrict__ W, const float4* __restrict__ M,
                          uint2* __restrict__ out, int n4) {
    int i = blockIdx.x * blockDim.x + threadIdx.x;
    if (i < n4) {
        float4 w = W[i], m = M[i];
        __nv_bfloat162 lo = __floats2bfloat162_rn(w.x * m.x, w.y * m.y);
        __nv_bfloat162 hi = __floats2bfloat162_rn(w.z * m.z, w.w * m.w);
        uint2 o;
        o.x = *reinterpret_cast<unsigned int*>(&lo);
        o.y = *reinterpret_cast<unsigned int*>(&hi);
        out[i] = o;
    }
}

__global__ void convert_k(const float4* __restrict__ W, uint2* __restrict__ out, int n4) {
    int i = blockIdx.x * blockDim.x + threadIdx.x;
    if (i < n4) {
        float4 w = W[i];
        __nv_bfloat162 lo = __floats2bfloat162_rn(w.x, w.y);
        __nv_bfloat162 hi = __floats2bfloat162_rn(w.z, w.w);
        uint2 o;
        o.x = *reinterpret_cast<unsigned int*>(&lo);
        o.y = *reinterpret_cast<unsigned int*>(&hi);
        out[i] = o;
    }
}

// ---------------- sparse one-hot column extraction ----------------
__global__ void extract_nz(const float* __restrict__ mask, int R,
                           int* __restrict__ idx, float* __restrict__ val, int* __restrict__ cnt) {
    int k = blockIdx.x;     // column 0..NK-1
    __shared__ int c;
    if (threadIdx.x == 0) c = 0;
    __syncthreads();
    for (int r = threadIdx.x; r < R; r += blockDim.x) {
        float v = mask[(size_t)r * NK + k];
        if (v != 0.0f) {
            int p = atomicAdd(&c, 1);
            if (p < CAP) { idx[k * CAP + p] = r; val[k * CAP + p] = v; }
        }
    }
    __syncthreads();
    if (threadIdx.x == 0) cnt[k] = (c < CAP) ? c : CAP;
}

__global__ void gather_kept(const float* __restrict__ X, int ld,
                            const int* __restrict__ idx, const float* __restrict__ val,
                            const int* __restrict__ cnt, float* __restrict__ kept) {
    int t = blockIdx.x * blockDim.x + threadIdx.x;    // b*NK + k
    if (t >= BB * NK) return;
    int b = t >> 5, k = t & 31;
    int n = cnt[k];
    float s = 0.0f;
    for (int i = 0; i < n; i++)
        s += val[k * CAP + i] * X[(size_t)b * ld + idx[k * CAP + i]];
    kept[t] = s;
}

// ---------------- bf16 wmma GEMM with fused epilogue ----------------
// C[m,n] = epi( sum_k A[m,k] * Bw[n,k] )
// MODE 0: y = sigmoid(acc + bias[n])
// MODE 1: y = res[m,n]*(v1[n]*v3[n]) + sigmoid(acc + bias[n])*(v2[n]*v3[n])
// MODE 2: y = sigmoid(acc + bias[n]) * v1[n]
#define BM 128
#define BN 128
#define BK 32
#define GEMM_SMEM 67584   // max(tiles=40960, stage=128*132*4=67584)

template<int MODE, bool WH>
__global__ void __launch_bounds__(256)
gemm_epi(const __nv_bfloat16* __restrict__ A,
         const __nv_bfloat16* __restrict__ Bw,
         float* __restrict__ C, __nv_bfloat16* __restrict__ Ch,
         const float* __restrict__ bias,
         const float* __restrict__ res,
         const float* __restrict__ v1, const float* __restrict__ v2, const float* __restrict__ v3,
         int M, int N, int K) {
    extern __shared__ unsigned char smem[];
    __nv_bfloat16* As = (__nv_bfloat16*)smem;          // [2][128][40]
    __nv_bfloat16* Bs = As + 2 * 128 * 40;             // [2][128][40]
    float* stage = (float*)smem;                        // [128][132]

    const int m0 = blockIdx.y * BM, n0 = blockIdx.x * BN;
    const int tid = threadIdx.x;
    const int wid = tid >> 5;
    const int wm = wid >> 1, wn = wid & 1;

    wmma::fragment<wmma::accumulator, 16, 16, 16, float> acc[2][4];
#pragma unroll
    for (int i = 0; i < 2; i++)
#pragma unroll
        for (int j = 0; j < 4; j++) wmma::fill_fragment(acc[i][j], 0.0f);

    auto loadTiles = [&](int kt, int buf) {
        int k0 = kt * BK;
#pragma unroll
        for (int u = 0; u < 2; u++) {
            int chunk = tid + u * 256;                 // 0..511
            int row = chunk >> 2, c4 = chunk & 3;      // 8 bf16 per chunk
            cp16(As + buf * 5120 + row * 40 + c4 * 8,
                 A + (size_t)(m0 + row) * K + k0 + c4 * 8);
            cp16(Bs + buf * 5120 + row * 40 + c4 * 8,
                 Bw + (size_t)(n0 + row) * K + k0 + c4 * 8);
        }
    };

    const int KT = K / BK;
    loadTiles(0, 0);
    cp_commit();
    cp_wait0();
    __syncthreads();

    for (int kt = 0; kt < KT; ++kt) {
        int cur = kt & 1;
        if (kt + 1 < KT) { loadTiles(kt + 1, cur ^ 1); cp_commit(); }
#pragma unroll
        for (int ks = 0; ks < 2; ++ks) {
            wmma::fragment<wmma::matrix_a, 16, 16, 16, __nv_bfloat16, wmma::row_major> af[2];
            wmma::fragment<wmma::matrix_b, 16, 16, 16, __nv_bfloat16, wmma::col_major> bf[4];
            const __nv_bfloat16* ap = As + cur * 5120 + (wm * 32) * 40 + ks * 16;
            wmma::load_matrix_sync(af[0], ap, 40);
            wmma::load_matrix_sync(af[1], ap + 16 * 40, 40);
            const __nv_bfloat16* bp = Bs + cur * 5120 + (wn * 64) * 40 + ks * 16;
#pragma unroll
            for (int j = 0; j < 4; j++) wmma::load_matrix_sync(bf[j], bp + j * 16 * 40, 40);
#pragma unroll
            for (int i = 0; i < 2; i++)
#pragma unroll
                for (int j = 0; j < 4; j++) wmma::mma_sync(acc[i][j], af[i], bf[j], acc[i][j]);
        }
        if (kt + 1 < KT) cp_wait0();
        __syncthreads();
    }

    // stage accumulators to smem, then fused elementwise epilogue
#pragma unroll
    for (int i = 0; i < 2; i++)
#pragma unroll
        for (int j = 0; j < 4; j++)
            wmma::store_matrix_sync(stage + (wm * 32 + 16 * i) * 132 + wn * 64 + 16 * j,
                                    acc[i][j], 132, wmma::mem_row_major);
    __syncthreads();

    for (int e = tid; e < BM * BN; e += 256) {
        int r = e >> 7, c = e & 127;
        int m = m0 + r, n = n0 + c;
        float z = stage[r * 132 + c] + bias[n];
        float y = sigf(z);
        if (MODE == 1) y = res[(size_t)m * N + n] * (v1[n] * v3[n]) + y * (v2[n] * v3[n]);
        else if (MODE == 2) y = y * v1[n];
        C[(size_t)m * N + n] = y;
        if (WH) Ch[(size_t)m * N + n] = __float2bfloat16(y);
    }
}

// ---------------- fused head: concat -> W6 -> sigmoid -> center -> W7 ----------------
__global__ void __launch_bounds__(256)
final_head(const float* __restrict__ A5,
           const float* __restrict__ kg, const float* __restrict__ ki,
           const float* __restrict__ kc, const float* __restrict__ kp,
           const float* __restrict__ clinn,
           const float* __restrict__ W6, const float* __restrict__ W7,
           float* __restrict__ out) {
    __shared__ float xc[16][400];
    __shared__ float lp[16][256];
    const int b0 = blockIdx.x * 16;
    const int t = threadIdx.x;

    for (int e = t; e < 16 * 400; e += 256) {
        int r = e / 400, c = e - r * 400;
        int b = b0 + r;
        float v;
        if (c < 256)      v = A5[(size_t)b * 256 + c];
        else if (c < 288) v = kg[b * NK + (c - 256)];
        else if (c < 320) v = ki[b * NK + (c - 288)];
        else if (c < 352) v = kc[b * NK + (c - 320)];
        else if (c < 384) v = kp[b * NK + (c - 352)];
        else              v = clinn[b * CLN + (c - 384)];
        xc[r][c] = v;
    }
    __syncthreads();

    float acc[16];
#pragma unroll
    for (int r = 0; r < 16; r++) acc[r] = 0.0f;
    const float* w6row = W6 + (size_t)t * 400;
    for (int c = 0; c < 400; c++) {
        float w = w6row[c];
#pragma unroll
        for (int r = 0; r < 16; r++) acc[r] += w * xc[r][c];
    }
#pragma unroll
    for (int r = 0; r < 16; r++) lp[r][t] = sigf(acc[r]);
    __syncthreads();

    int wid = t >> 5, lane = t & 31;
#pragma unroll
    for (int rr = 0; rr < 2; rr++) {
        int r = wid * 2 + rr;
        float s1 = 0.0f, s2 = 0.0f, sw = 0.0f;
        for (int i = lane; i < 256; i += 32) {
            float l = lp[r][i];
            float w7 = W7[i];
            s1 += l; s2 += l * w7; sw += w7;
        }
#pragma unroll
        for (int off = 16; off; off >>= 1) {
            s1 += __shfl_down_sync(0xffffffff, s1, off);
            s2 += __shfl_down_sync(0xffffffff, s2, off);
            sw += __shfl_down_sync(0xffffffff, sw, off);
        }
        if (lane == 0) out[b0 + r] = s2 - (s1 * (1.0f / 256.0f)) * sw;
    }
}

// ---------------- host ----------------
extern "C" void kernel_launch(void* const* d_in, const int* in_sizes, int n_in,
                              void* d_out, int out_size) {
    const float* x_gene   = (const float*)d_in[0];
    const float* x_invmea = (const float*)d_in[1];
    const float* x_curv   = (const float*)d_in[2];
    const float* clinn    = (const float*)d_in[3];
    const float* Adj      = (const float*)d_in[4];
    const float* edge_m   = (const float*)d_in[5];
    const float* path_m   = (const float*)d_in[6];
    const float* tg       = (const float*)d_in[7];
    const float* ti       = (const float*)d_in[8];
    const float* tc       = (const float*)d_in[9];
    const float* tp       = (const float*)d_in[10];
    const float* W1 = (const float*)d_in[11]; const float* b1 = (const float*)d_in[12];
    const float* W2 = (const float*)d_in[13]; const float* b2 = (const float*)d_in[14];
    const float* W3 = (const float*)d_in[15]; const float* b3 = (const float*)d_in[16];
    const float* W4 = (const float*)d_in[17]; const float* b4 = (const float*)d_in[18];
    const float* W5 = (const float*)d_in[19]; const float* b5 = (const float*)d_in[20];
    const float* W6 = (const float*)d_in[21]; const float* W7 = (const float*)d_in[22];
    const float* mp11 = (const float*)d_in[23]; const float* mp12 = (const float*)d_in[24];
    const float* mp1  = (const float*)d_in[25];
    const float* mp21 = (const float*)d_in[26]; const float* mp22 = (const float*)d_in[27];
    const float* mp2  = (const float*)d_in[28];
    const float* mp3  = (const float*)d_in[29];
    float* out = (float*)d_out;

    // resolve scratch symbol addresses (host-side; runs only at capture time)
    void* p;
    cudaGetSymbolAddress(&p, g_W1h); __nv_bfloat16* W1h = (__nv_bfloat16*)p;
    cudaGetSymbolAddress(&p, g_W2h); __nv_bfloat16* W2h = (__nv_bfloat16*)p;
    cudaGetSymbolAddress(&p, g_W3h); __nv_bfloat16* W3h = (__nv_bfloat16*)p;
    cudaGetSymbolAddress(&p, g_W4h); __nv_bfloat16* W4h = (__nv_bfloat16*)p;
    cudaGetSymbolAddress(&p, g_W5h); __nv_bfloat16* W5h = (__nv_bfloat16*)p;
    cudaGetSymbolAddress(&p, g_Xgh); __nv_bfloat16* Xgh = (__nv_bfloat16*)p;
    cudaGetSymbolAddress(&p, g_A1);  float* A1  = (float*)p;
    cudaGetSymbolAddress(&p, g_A1h); __nv_bfloat16* A1h = (__nv_bfloat16*)p;
    cudaGetSymbolAddress(&p, g_A2);  float* A2  = (float*)p;
    cudaGetSymbolAddress(&p, g_A2h); __nv_bfloat16* A2h = (__nv_bfloat16*)p;
    cudaGetSymbolAddress(&p, g_A3);  float* A3  = (float*)p;
    cudaGetSymbolAddress(&p, g_A3h); __nv_bfloat16* A3h = (__nv_bfloat16*)p;
    cudaGetSymbolAddress(&p, g_A4);  float* A4  = (float*)p;
    cudaGetSymbolAddress(&p, g_A4h); __nv_bfloat16* A4h = (__nv_bfloat16*)p;
    cudaGetSymbolAddress(&p, g_A5);  float* A5  = (float*)p;
    cudaGetSymbolAddress(&p, g_kept); float* kept = (float*)p;
    cudaGetSymbolAddress(&p, g_nzi); int* nzi = (int*)p;
    cudaGetSymbolAddress(&p, g_nzv); float* nzv = (float*)p;
    cudaGetSymbolAddress(&p, g_nzc); int* nzc = (int*)p;

    float* kg = kept + 0 * BB * NK;
    float* ki = kept + 1 * BB * NK;
    float* kc = kept + 2 * BB * NK;
    float* kp = kept + 3 * BB * NK;

    cudaFuncSetAttribute(gemm_epi<0, true >, cudaFuncAttributeMaxDynamicSharedMemorySize, GEMM_SMEM);
    cudaFuncSetAttribute(gemm_epi<0, false>, cudaFuncAttributeMaxDynamicSharedMemorySize, GEMM_SMEM);
    cudaFuncSetAttribute(gemm_epi<1, true >, cudaFuncAttributeMaxDynamicSharedMemorySize, GEMM_SMEM);
    cudaFuncSetAttribute(gemm_epi<2, true >, cudaFuncAttributeMaxDynamicSharedMemorySize, GEMM_SMEM);

    // 1) premask / convert weights + x_gene to bf16
    {
        int n4;
        n4 = IN * IN / 4;         premask_k<<<n4 / 256, 256>>>((const float4*)W1, (const float4*)Adj,    (uint2*)W1h, n4);
        n4 = ED * IN / 4;         premask_k<<<n4 / 256, 256>>>((const float4*)W2, (const float4*)edge_m, (uint2*)W2h, n4);
        n4 = PW * ED / 4;         premask_k<<<n4 / 256, 256>>>((const float4*)W3, (const float4*)path_m, (uint2*)W3h, n4);
        n4 = OUTD * PW / 4;       convert_k<<<n4 / 256, 256>>>((const float4*)W4, (uint2*)W4h, n4);
        n4 = OUTD * OUTD / 4;     convert_k<<<n4 / 256, 256>>>((const float4*)W5, (uint2*)W5h, n4);
        n4 = BB * IN / 4;         convert_k<<<n4 / 256, 256>>>((const float4*)x_gene, (uint2*)Xgh, n4);
    }

    // 2) extract one-hot columns of the four top_* masks
    extract_nz<<<NK, 256>>>(tg, IN, nzi + 0 * NK * CAP, nzv + 0 * NK * CAP, nzc + 0 * NK);
    extract_nz<<<NK, 256>>>(ti, IN, nzi + 1 * NK * CAP, nzv + 1 * NK * CAP, nzc + 1 * NK);
    extract_nz<<<NK, 256>>>(tc, ED, nzi + 2 * NK * CAP, nzv + 2 * NK * CAP, nzc + 2 * NK);
    extract_nz<<<NK, 256>>>(tp, PW, nzi + 3 * NK * CAP, nzv + 3 * NK * CAP, nzc + 3 * NK);

    // kept_gene from raw x_gene
    gather_kept<<<BB * NK / 256, 256>>>(x_gene, IN, nzi + 0 * NK * CAP, nzv + 0 * NK * CAP, nzc + 0 * NK, kg);

    // 3) layer 1: x1 = mix(x_invmea, sigmoid(x_gene @ W1m^T + b1))
    {
        dim3 grid(IN / BN, BB / BM);
        gemm_epi<1, true><<<grid, 256, GEMM_SMEM>>>(Xgh, W1h, A1, A1h, b1, x_invmea, mp11, mp12, mp1, BB, IN, IN);
    }
    gather_kept<<<BB * NK / 256, 256>>>(A1, IN, nzi + 1 * NK * CAP, nzv + 1 * NK * CAP, nzc + 1 * NK, ki);

    // 4) layer 2: x1 = mix(x_curv, sigmoid(x1 @ W2m^T + b2))
    {
        dim3 grid(ED / BN, BB / BM);
        gemm_epi<1, true><<<grid, 256, GEMM_SMEM>>>(A1h, W2h, A2, A2h, b2, x_curv, mp21, mp22, mp2, BB, ED, IN);
    }
    gather_kept<<<BB * NK / 256, 256>>>(A2, ED, nzi + 2 * NK * CAP, nzv + 2 * NK * CAP, nzc + 2 * NK, kc);

    // 5) layer 3: x1 = sigmoid(x1 @ W3m^T + b3) * mp3
    {
        dim3 grid(PW / BN, BB / BM);
        gemm_epi<2, true><<<grid, 256, GEMM_SMEM>>>(A2h, W3h, A3, A3h, b3, nullptr, mp3, nullptr, nullptr, BB, PW, ED);
    }
    gather_kept<<<BB * NK / 256, 256>>>(A3, PW, nzi + 3 * NK * CAP, nzv + 3 * NK * CAP, nzc + 3 * NK, kp);

    // 6) layer 4: sigmoid(x1 @ W4^T + b4)
    {
        dim3 grid(OUTD / BN, BB / BM);
        gemm_epi<0, true><<<grid, 256, GEMM_SMEM>>>(A3h, W4h, A4, A4h, b4, nullptr, nullptr, nullptr, nullptr, BB, OUTD, PW);
    }
    // 7) layer 5: sigmoid(x1 @ W5^T + b5)
    {
        dim3 grid(OUTD / BN, BB / BM);
        gemm_epi<0, false><<<grid, 256, GEMM_SMEM>>>(A4h, W5h, A5, nullptr, b5, nullptr, nullptr, nullptr, nullptr, BB, OUTD, OUTD);
    }

    // 8) fused head: concat -> W6 -> sigmoid -> center -> W7
    final_head<<<BB / 16, 256>>>(A5, kg, ki, kc, kp, clinn, W6, W7, out);
}

// round 4
// speedup vs baseline: 2.4470x; 2.4470x over previous
#include <cuda_runtime.h>
#include <cuda_bf16.h>
#include <mma.h>
#include <cstdint>
#include <cstddef>

using namespace nvcuda;

// ---------------- problem constants ----------------
#define BB  2048
#define IN  4096
#define ED  8192
#define PW  2048
#define OUTD 256
#define CLN 16
#define NK  32
#define CAP 512

// CSR caps (binomial nnz/row: mean 42/20/164, max over rows ~66/40/215)
#define CAP1 192
#define CAP2 160
#define CAP3 448
#define CAPMAX 448

// ---------------- device scratch (allowed: __device__ globals) ----------------
// CSR for the three masked weight matrices
__device__ int   g_i1[(size_t)IN * CAP1];
__device__ float g_wv1[(size_t)IN * CAP1];
__device__ int   g_c1[IN];
__device__ int   g_i2[(size_t)ED * CAP2];
__device__ float g_wv2[(size_t)ED * CAP2];
__device__ int   g_c2[ED];
__device__ int   g_i3[(size_t)PW * CAP3];
__device__ float g_wv3[(size_t)PW * CAP3];
__device__ int   g_c3[PW];

// transposed activations
__device__ __nv_bfloat16 g_xgT [(size_t)IN * BB];   // x_gene^T bf16
__device__ float         g_ximT[(size_t)IN * BB];   // x_invmea^T fp32
__device__ float         g_xcvT[(size_t)ED * BB];   // x_curv^T fp32
__device__ __nv_bfloat16 g_y1Th[(size_t)IN * BB];
__device__ float         g_y1Tf[(size_t)IN * BB];
__device__ __nv_bfloat16 g_y2Th[(size_t)ED * BB];
__device__ float         g_y2Tf[(size_t)ED * BB];
__device__ __nv_bfloat16 g_y3Th[(size_t)PW * BB];
__device__ float         g_y3Tf[(size_t)PW * BB];

// small dense tail
__device__ __nv_bfloat16 g_A3h[(size_t)BB * PW];
__device__ __nv_bfloat16 g_W4h[(size_t)OUTD * PW];
__device__ __nv_bfloat16 g_W5h[(size_t)OUTD * OUTD];
__device__ float         g_A4 [(size_t)BB * OUTD];
__device__ __nv_bfloat16 g_A4h[(size_t)BB * OUTD];
__device__ float         g_A5 [(size_t)BB * OUTD];

// one-hot kept machinery
__device__ float g_kept[4][BB * NK];
__device__ int   g_nzi[4][NK * CAP];
__device__ float g_nzv[4][NK * CAP];
__device__ int   g_nzc[4][NK];

// ---------------- helpers ----------------
__device__ __forceinline__ float sigf(float x) { return 1.0f / (1.0f + __expf(-x)); }

__device__ __forceinline__ void cp16(void* s, const void* g) {
    unsigned sa = (unsigned)__cvta_generic_to_shared(s);
    asm volatile("cp.async.cg.shared.global [%0], [%1], 16;\n" :: "r"(sa), "l"(g) : "memory");
}
__device__ __forceinline__ void cp_commit() { asm volatile("cp.async.commit_group;\n" ::: "memory"); }
__device__ __forceinline__ void cp_wait0()  { asm volatile("cp.async.wait_group 0;\n" ::: "memory"); }

// ---------------- deterministic CSR extraction: warp per row ----------------
// val = W[n,k] * M[n,k] for M!=0, column order ascending (ballot+prefix => deterministic)
__global__ void extract_csr(const float* __restrict__ W, const float* __restrict__ M,
                            int C, int cap,
                            int* __restrict__ idx, float* __restrict__ val, int* __restrict__ cnt) {
    int row  = blockIdx.x * (blockDim.x >> 5) + (threadIdx.x >> 5);
    int lane = threadIdx.x & 31;
    size_t rb = (size_t)row * C;
    int base = row * cap;
    int count = 0;
    for (int c0 = 0; c0 < C; c0 += 32) {
        float m = M[rb + c0 + lane];
        unsigned bal = __ballot_sync(0xffffffffu, m != 0.0f);
        if (m != 0.0f) {
            int pos = count + __popc(bal & ((1u << lane) - 1u));
            if (pos < cap) {
                idx[base + pos] = c0 + lane;
                val[base + pos] = W[rb + c0 + lane] * m;
            }
        }
        count += __popc(bal);
    }
    if (lane == 0) cnt[row] = (count < cap) ? count : cap;
}

// ---------------- transposes (32x32 tiles) ----------------
__global__ void transpose_f2h(const float* __restrict__ in, __nv_bfloat16* __restrict__ out,
                              int R, int C) {       // in [R,C] -> out [C,R]
    __shared__ float t[32][33];
    int c0 = blockIdx.x * 32, r0 = blockIdx.y * 32;
    int x = threadIdx.x, y = threadIdx.y;
#pragma unroll
    for (int i = 0; i < 32; i += 8)
        t[y + i][x] = in[(size_t)(r0 + y + i) * C + c0 + x];
    __syncthreads();
#pragma unroll
    for (int i = 0; i < 32; i += 8)
        out[(size_t)(c0 + y + i) * R + r0 + x] = __float2bfloat16(t[x][y + i]);
}

__global__ void transpose_f2f(const float* __restrict__ in, float* __restrict__ out,
                              int R, int C) {
    __shared__ float t[32][33];
    int c0 = blockIdx.x * 32, r0 = blockIdx.y * 32;
    int x = threadIdx.x, y = threadIdx.y;
#pragma unroll
    for (int i = 0; i < 32; i += 8)
        t[y + i][x] = in[(size_t)(r0 + y + i) * C + c0 + x];
    __syncthreads();
#pragma unroll
    for (int i = 0; i < 32; i += 8)
        out[(size_t)(c0 + y + i) * R + r0 + x] = t[x][y + i];
}

__global__ void transpose_h2h(const __nv_bfloat16* __restrict__ in, __nv_bfloat16* __restrict__ out,
                              int R, int C) {
    __shared__ __nv_bfloat16 t[32][33];
    int c0 = blockIdx.x * 32, r0 = blockIdx.y * 32;
    int x = threadIdx.x, y = threadIdx.y;
#pragma unroll
    for (int i = 0; i < 32; i += 8)
        t[y + i][x] = in[(size_t)(r0 + y + i) * C + c0 + x];
    __syncthreads();
#pragma unroll
    for (int i = 0; i < 32; i += 8)
        out[(size_t)(c0 + y + i) * R + r0 + x] = t[x][y + i];
}

// ---------------- SpMM with fused epilogue ----------------
// CTA = one output row n, 256 threads x 8 batch elems (B=2048).
// z[b] = sum_j wval[j] * xT[idx[j], b] + bias[n]
// MODE 1: y = resT[n,b]*(v1[n]*v3[n]) + sig(z)*(v2[n]*v3[n])
// MODE 2: y = sig(z)*v1[n]
template<int MODE>
__global__ void __launch_bounds__(256)
spmm_epi(const int* __restrict__ idx, const float* __restrict__ val,
         const int* __restrict__ cnt, int cap,
         const __nv_bfloat16* __restrict__ xT,
         const float* __restrict__ bias,
         const float* __restrict__ resT,
         const float* __restrict__ v1, const float* __restrict__ v2, const float* __restrict__ v3,
         float* __restrict__ yTf, __nv_bfloat16* __restrict__ yTh) {
    __shared__ int   sidx[CAPMAX];
    __shared__ float sval[CAPMAX];
    const int n = blockIdx.x;
    const int tid = threadIdx.x;
    const int nnz = cnt[n];
    for (int i = tid; i < nnz; i += 256) {
        sidx[i] = idx[(size_t)n * cap + i];
        sval[i] = val[(size_t)n * cap + i];
    }
    __syncthreads();

    float acc[8];
#pragma unroll
    for (int i = 0; i < 8; i++) acc[i] = 0.0f;

#pragma unroll 4
    for (int j = 0; j < nnz; j++) {
        int k = sidx[j];
        float w = sval[j];
        uint4 pv = *((const uint4*)(xT + ((size_t)k << 11)) + tid);
        const __nv_bfloat162* h = (const __nv_bfloat162*)&pv;
#pragma unroll
        for (int i = 0; i < 4; i++) {
            float2 f = __bfloat1622float2(h[i]);
            acc[2 * i + 0] = fmaf(w, f.x, acc[2 * i + 0]);
            acc[2 * i + 1] = fmaf(w, f.y, acc[2 * i + 1]);
        }
    }

    const float bi = bias[n];
    float c1 = 0.0f, c2 = 0.0f;
    if (MODE == 1) { c1 = v1[n] * v3[n]; c2 = v2[n] * v3[n]; }
    else           { c1 = v1[n]; }

    float y[8];
    if (MODE == 1) {
        float2 r[4];
        const float4* rp = (const float4*)(resT + ((size_t)n << 11)) + tid * 2;
        float4 ra = rp[0], rb = rp[1];
        r[0] = make_float2(ra.x, ra.y); r[1] = make_float2(ra.z, ra.w);
        r[2] = make_float2(rb.x, rb.y); r[3] = make_float2(rb.z, rb.w);
#pragma unroll
        for (int i = 0; i < 4; i++) {
            y[2 * i + 0] = r[i].x * c1 + sigf(acc[2 * i + 0] + bi) * c2;
            y[2 * i + 1] = r[i].y * c1 + sigf(acc[2 * i + 1] + bi) * c2;
        }
    } else {
#pragma unroll
        for (int i = 0; i < 8; i++) y[i] = sigf(acc[i] + bi) * c1;
    }

    // fp32 out (for exact kept gathers)
    float4* of = (float4*)(yTf + ((size_t)n << 11)) + tid * 2;
    of[0] = make_float4(y[0], y[1], y[2], y[3]);
    of[1] = make_float4(y[4], y[5], y[6], y[7]);
    // bf16 out (next SpMM / transpose)
    uint4 oh;
    __nv_bfloat162 h0 = __floats2bfloat162_rn(y[0], y[1]);
    __nv_bfloat162 h1 = __floats2bfloat162_rn(y[2], y[3]);
    __nv_bfloat162 h2 = __floats2bfloat162_rn(y[4], y[5]);
    __nv_bfloat162 h3 = __floats2bfloat162_rn(y[6], y[7]);
    oh.x = *(unsigned*)&h0; oh.y = *(unsigned*)&h1;
    oh.z = *(unsigned*)&h2; oh.w = *(unsigned*)&h3;
    *((uint4*)(yTh + ((size_t)n << 11)) + tid) = oh;
}

// ---------------- fp32 -> bf16 convert ----------------
__global__ void convert_k(const float4* __restrict__ W, uint2* __restrict__ out, int n4) {
    int i = blockIdx.x * blockDim.x + threadIdx.x;
    if (i < n4) {
        float4 w = W[i];
        __nv_bfloat162 lo = __floats2bfloat162_rn(w.x, w.y);
        __nv_bfloat162 hi = __floats2bfloat162_rn(w.z, w.w);
        uint2 o;
        o.x = *reinterpret_cast<unsigned int*>(&lo);
        o.y = *reinterpret_cast<unsigned int*>(&hi);
        out[i] = o;
    }
}

// ---------------- sparse one-hot column extraction (top_* masks) ----------------
__global__ void extract_nz(const float* __restrict__ mask, int R,
                           int* __restrict__ idx, float* __restrict__ val, int* __restrict__ cnt) {
    int k = blockIdx.x;
    __shared__ int c;
    if (threadIdx.x == 0) c = 0;
    __syncthreads();
    for (int r = threadIdx.x; r < R; r += blockDim.x) {
        float v = mask[(size_t)r * NK + k];
        if (v != 0.0f) {
            int p = atomicAdd(&c, 1);
            if (p < CAP) { idx[k * CAP + p] = r; val[k * CAP + p] = v; }
        }
    }
    __syncthreads();
    if (threadIdx.x == 0) cnt[k] = (c < CAP) ? c : CAP;
}

// gather from row-major X [B, ld]
__global__ void gather_kept(const float* __restrict__ X, int ld,
                            const int* __restrict__ idx, const float* __restrict__ val,
                            const int* __restrict__ cnt, float* __restrict__ kept) {
    int t = blockIdx.x * blockDim.x + threadIdx.x;
    if (t >= BB * NK) return;
    int b = t >> 5, k = t & 31;
    int n = cnt[k];
    float s = 0.0f;
    for (int i = 0; i < n; i++)
        s += val[k * CAP + i] * X[(size_t)b * ld + idx[k * CAP + i]];
    kept[t] = s;
}

// gather from transposed fp32 XT [R, B] -> kept [B, NK] (coalesced reads)
__global__ void gather_keptT(const float* __restrict__ XT,
                             const int* __restrict__ idx, const float* __restrict__ val,
                             const int* __restrict__ cnt, float* __restrict__ kept) {
    int t = blockIdx.x * blockDim.x + threadIdx.x;
    if (t >= NK * BB) return;
    int k = t >> 11, b = t & (BB - 1);
    int n = cnt[k];
    float s = 0.0f;
    for (int i = 0; i < n; i++)
        s += val[k * CAP + i] * XT[((size_t)idx[k * CAP + i] << 11) + b];
    kept[b * NK + k] = s;
}

// ---------------- bf16 wmma GEMM with fused epilogue (small tail layers) ----------------
#define BM 128
#define BN 128
#define BK 32
#define GEMM_SMEM 67584

template<int MODE, bool WH>
__global__ void __launch_bounds__(256)
gemm_epi(const __nv_bfloat16* __restrict__ A,
         const __nv_bfloat16* __restrict__ Bw,
         float* __restrict__ C, __nv_bfloat16* __restrict__ Ch,
         const float* __restrict__ bias,
         int M, int N, int K) {
    extern __shared__ unsigned char smem[];
    __nv_bfloat16* As = (__nv_bfloat16*)smem;
    __nv_bfloat16* Bs = As + 2 * 128 * 40;
    float* stage = (float*)smem;

    const int m0 = blockIdx.y * BM, n0 = blockIdx.x * BN;
    const int tid = threadIdx.x;
    const int wid = tid >> 5;
    const int wm = wid >> 1, wn = wid & 1;

    wmma::fragment<wmma::accumulator, 16, 16, 16, float> acc[2][4];
#pragma unroll
    for (int i = 0; i < 2; i++)
#pragma unroll
        for (int j = 0; j < 4; j++) wmma::fill_fragment(acc[i][j], 0.0f);

    auto loadTiles = [&](int kt, int buf) {
        int k0 = kt * BK;
#pragma unroll
        for (int u = 0; u < 2; u++) {
            int chunk = tid + u * 256;
            int row = chunk >> 2, c4 = chunk & 3;
            cp16(As + buf * 5120 + row * 40 + c4 * 8,
                 A + (size_t)(m0 + row) * K + k0 + c4 * 8);
            cp16(Bs + buf * 5120 + row * 40 + c4 * 8,
                 Bw + (size_t)(n0 + row) * K + k0 + c4 * 8);
        }
    };

    const int KT = K / BK;
    loadTiles(0, 0);
    cp_commit();
    cp_wait0();
    __syncthreads();

    for (int kt = 0; kt < KT; ++kt) {
        int cur = kt & 1;
        if (kt + 1 < KT) { loadTiles(kt + 1, cur ^ 1); cp_commit(); }
#pragma unroll
        for (int ks = 0; ks < 2; ++ks) {
            wmma::fragment<wmma::matrix_a, 16, 16, 16, __nv_bfloat16, wmma::row_major> af[2];
            wmma::fragment<wmma::matrix_b, 16, 16, 16, __nv_bfloat16, wmma::col_major> bf[4];
            const __nv_bfloat16* ap = As + cur * 5120 + (wm * 32) * 40 + ks * 16;
            wmma::load_matrix_sync(af[0], ap, 40);
            wmma::load_matrix_sync(af[1], ap + 16 * 40, 40);
            const __nv_bfloat16* bp = Bs + cur * 5120 + (wn * 64) * 40 + ks * 16;
#pragma unroll
            for (int j = 0; j < 4; j++) wmma::load_matrix_sync(bf[j], bp + j * 16 * 40, 40);
#pragma unroll
            for (int i = 0; i < 2; i++)
#pragma unroll
                for (int j = 0; j < 4; j++) wmma::mma_sync(acc[i][j], af[i], bf[j], acc[i][j]);
        }
        if (kt + 1 < KT) cp_wait0();
        __syncthreads();
    }

#pragma unroll
    for (int i = 0; i < 2; i++)
#pragma unroll
        for (int j = 0; j < 4; j++)
            wmma::store_matrix_sync(stage + (wm * 32 + 16 * i) * 132 + wn * 64 + 16 * j,
                                    acc[i][j], 132, wmma::mem_row_major);
    __syncthreads();

    for (int e = tid; e < BM * BN; e += 256) {
        int r = e >> 7, c = e & 127;
        int m = m0 + r, n = n0 + c;
        float z = stage[r * 132 + c] + bias[n];
        float y = sigf(z);
        C[(size_t)m * N + n] = y;
        if (WH) Ch[(size_t)m * N + n] = __float2bfloat16(y);
    }
}

// ---------------- fused head: concat -> W6 -> sigmoid -> center -> W7 ----------------
__global__ void __launch_bounds__(256)
final_head(const float* __restrict__ A5,
           const float* __restrict__ kg, const float* __restrict__ ki,
           const float* __restrict__ kc, const float* __restrict__ kp,
           const float* __restrict__ clinn,
           const float* __restrict__ W6, const float* __restrict__ W7,
           float* __restrict__ out) {
    __shared__ float xc[16][400];
    __shared__ float lp[16][256];
    const int b0 = blockIdx.x * 16;
    const int t = threadIdx.x;

    for (int e = t; e < 16 * 400; e += 256) {
        int r = e / 400, c = e - r * 400;
        int b = b0 + r;
        float v;
        if (c < 256)      v = A5[(size_t)b * 256 + c];
        else if (c < 288) v = kg[b * NK + (c - 256)];
        else if (c < 320) v = ki[b * NK + (c - 288)];
        else if (c < 352) v = kc[b * NK + (c - 320)];
        else if (c < 384) v = kp[b * NK + (c - 352)];
        else              v = clinn[b * CLN + (c - 384)];
        xc[r][c] = v;
    }
    __syncthreads();

    float acc[16];
#pragma unroll
    for (int r = 0; r < 16; r++) acc[r] = 0.0f;
    const float* w6row = W6 + (size_t)t * 400;
    for (int c = 0; c < 400; c++) {
        float w = w6row[c];
#pragma unroll
        for (int r = 0; r < 16; r++) acc[r] += w * xc[r][c];
    }
#pragma unroll
    for (int r = 0; r < 16; r++) lp[r][t] = sigf(acc[r]);
    __syncthreads();

    int wid = t >> 5, lane = t & 31;
#pragma unroll
    for (int rr = 0; rr < 2; rr++) {
        int r = wid * 2 + rr;
        float s1 = 0.0f, s2 = 0.0f, sw = 0.0f;
        for (int i = lane; i < 256; i += 32) {
            float l = lp[r][i];
            float w7 = W7[i];
            s1 += l; s2 += l * w7; sw += w7;
        }
#pragma unroll
        for (int off = 16; off; off >>= 1) {
            s1 += __shfl_down_sync(0xffffffff, s1, off);
            s2 += __shfl_down_sync(0xffffffff, s2, off);
            sw += __shfl_down_sync(0xffffffff, sw, off);
        }
        if (lane == 0) out[b0 + r] = s2 - (s1 * (1.0f / 256.0f)) * sw;
    }
}

// ---------------- host ----------------
extern "C" void kernel_launch(void* const* d_in, const int* in_sizes, int n_in,
                              void* d_out, int out_size) {
    const float* x_gene   = (const float*)d_in[0];
    const float* x_invmea = (const float*)d_in[1];
    const float* x_curv   = (const float*)d_in[2];
    const float* clinn    = (const float*)d_in[3];
    const float* Adj      = (const float*)d_in[4];
    const float* edge_m   = (const float*)d_in[5];
    const float* path_m   = (const float*)d_in[6];
    const float* tg       = (const float*)d_in[7];
    const float* ti       = (const float*)d_in[8];
    const float* tc       = (const float*)d_in[9];
    const float* tp       = (const float*)d_in[10];
    const float* W1 = (const float*)d_in[11]; const float* b1 = (const float*)d_in[12];
    const float* W2 = (const float*)d_in[13]; const float* b2 = (const float*)d_in[14];
    const float* W3 = (const float*)d_in[15]; const float* b3 = (const float*)d_in[16];
    const float* W4 = (const float*)d_in[17]; const float* b4 = (const float*)d_in[18];
    const float* W5 = (const float*)d_in[19]; const float* b5 = (const float*)d_in[20];
    const float* W6 = (const float*)d_in[21]; const float* W7 = (const float*)d_in[22];
    const float* mp11 = (const float*)d_in[23]; const float* mp12 = (const float*)d_in[24];
    const float* mp1  = (const float*)d_in[25];
    const float* mp21 = (const float*)d_in[26]; const float* mp22 = (const float*)d_in[27];
    const float* mp2  = (const float*)d_in[28];
    const float* mp3  = (const float*)d_in[29];
    float* out = (float*)d_out;

    void* p;
    cudaGetSymbolAddress(&p, g_i1);  int* i1 = (int*)p;
    cudaGetSymbolAddress(&p, g_wv1); float* wv1 = (float*)p;
    cudaGetSymbolAddress(&p, g_c1);  int* c1 = (int*)p;
    cudaGetSymbolAddress(&p, g_i2);  int* i2 = (int*)p;
    cudaGetSymbolAddress(&p, g_wv2); float* wv2 = (float*)p;
    cudaGetSymbolAddress(&p, g_c2);  int* c2 = (int*)p;
    cudaGetSymbolAddress(&p, g_i3);  int* i3 = (int*)p;
    cudaGetSymbolAddress(&p, g_wv3); float* wv3 = (float*)p;
    cudaGetSymbolAddress(&p, g_c3);  int* c3 = (int*)p;
    cudaGetSymbolAddress(&p, g_xgT);  __nv_bfloat16* xgT = (__nv_bfloat16*)p;
    cudaGetSymbolAddress(&p, g_ximT); float* ximT = (float*)p;
    cudaGetSymbolAddress(&p, g_xcvT); float* xcvT = (float*)p;
    cudaGetSymbolAddress(&p, g_y1Th); __nv_bfloat16* y1Th = (__nv_bfloat16*)p;
    cudaGetSymbolAddress(&p, g_y1Tf); float* y1Tf = (float*)p;
    cudaGetSymbolAddress(&p, g_y2Th); __nv_bfloat16* y2Th = (__nv_bfloat16*)p;
    cudaGetSymbolAddress(&p, g_y2Tf); float* y2Tf = (float*)p;
    cudaGetSymbolAddress(&p, g_y3Th); __nv_bfloat16* y3Th = (__nv_bfloat16*)p;
    cudaGetSymbolAddress(&p, g_y3Tf); float* y3Tf = (float*)p;
    cudaGetSymbolAddress(&p, g_A3h); __nv_bfloat16* A3h = (__nv_bfloat16*)p;
    cudaGetSymbolAddress(&p, g_W4h); __nv_bfloat16* W4h = (__nv_bfloat16*)p;
    cudaGetSymbolAddress(&p, g_W5h); __nv_bfloat16* W5h = (__nv_bfloat16*)p;
    cudaGetSymbolAddress(&p, g_A4);  float* A4 = (float*)p;
    cudaGetSymbolAddress(&p, g_A4h); __nv_bfloat16* A4h = (__nv_bfloat16*)p;
    cudaGetSymbolAddress(&p, g_A5);  float* A5 = (float*)p;
    cudaGetSymbolAddress(&p, g_kept); float* kept = (float*)p;
    cudaGetSymbolAddress(&p, g_nzi); int* nzi = (int*)p;
    cudaGetSymbolAddress(&p, g_nzv); float* nzv = (float*)p;
    cudaGetSymbolAddress(&p, g_nzc); int* nzc = (int*)p;

    float* kg = kept + 0 * BB * NK;
    float* ki = kept + 1 * BB * NK;
    float* kc = kept + 2 * BB * NK;
    float* kp = kept + 3 * BB * NK;

    cudaFuncSetAttribute(gemm_epi<0, true >, cudaFuncAttributeMaxDynamicSharedMemorySize, GEMM_SMEM);
    cudaFuncSetAttribute(gemm_epi<0, false>, cudaFuncAttributeMaxDynamicSharedMemorySize, GEMM_SMEM);

    // 1) CSR extraction of the masked weights (deterministic order)
    extract_csr<<<IN / 8, 256>>>(W1, Adj,    IN, CAP1, i1, wv1, c1);
    extract_csr<<<ED / 8, 256>>>(W2, edge_m, IN, CAP2, i2, wv2, c2);
    extract_csr<<<PW / 8, 256>>>(W3, path_m, ED, CAP3, i3, wv3, c3);

    // 2) convert small dense weights
    convert_k<<<OUTD * PW / 4 / 256, 256>>>((const float4*)W4, (uint2*)W4h, OUTD * PW / 4);
    convert_k<<<OUTD * OUTD / 4 / 256, 256>>>((const float4*)W5, (uint2*)W5h, OUTD * OUTD / 4);

    // 3) transpose inputs
    {
        dim3 blk(32, 8);
        transpose_f2h<<<dim3(IN / 32, BB / 32), blk>>>(x_gene,   xgT,  BB, IN);
        transpose_f2f<<<dim3(IN / 32, BB / 32), blk>>>(x_invmea, ximT, BB, IN);
        transpose_f2f<<<dim3(ED / 32, BB / 32), blk>>>(x_curv,   xcvT, BB, ED);
    }

    // 4) one-hot top_* masks + kept_gene
    extract_nz<<<NK, 256>>>(tg, IN, nzi + 0 * NK * CAP, nzv + 0 * NK * CAP, nzc + 0 * NK);
    extract_nz<<<NK, 256>>>(ti, IN, nzi + 1 * NK * CAP, nzv + 1 * NK * CAP, nzc + 1 * NK);
    extract_nz<<<NK, 256>>>(tc, ED, nzi + 2 * NK * CAP, nzv + 2 * NK * CAP, nzc + 2 * NK);
    extract_nz<<<NK, 256>>>(tp, PW, nzi + 3 * NK * CAP, nzv + 3 * NK * CAP, nzc + 3 * NK);
    gather_kept<<<BB * NK / 256, 256>>>(x_gene, IN, nzi + 0 * NK * CAP, nzv + 0 * NK * CAP, nzc + 0 * NK, kg);

    // 5) layer 1 (SpMM): y1 = mix(x_invmea, sig(x_gene @ W1m^T + b1))
    spmm_epi<1><<<IN, 256>>>(i1, wv1, c1, CAP1, xgT, b1, ximT, mp11, mp12, mp1, y1Tf, y1Th);
    gather_keptT<<<NK * BB / 256, 256>>>(y1Tf, nzi + 1 * NK * CAP, nzv + 1 * NK * CAP, nzc + 1 * NK, ki);

    // 6) layer 2 (SpMM): y2 = mix(x_curv, sig(y1 @ W2m^T + b2))
    spmm_epi<1><<<ED, 256>>>(i2, wv2, c2, CAP2, y1Th, b2, xcvT, mp21, mp22, mp2, y2Tf, y2Th);
    gather_keptT<<<NK * BB / 256, 256>>>(y2Tf, nzi + 2 * NK * CAP, nzv + 2 * NK * CAP, nzc + 2 * NK, kc);

    // 7) layer 3 (SpMM): y3 = sig(y2 @ W3m^T + b3) * mp3
    spmm_epi<2><<<PW, 256>>>(i3, wv3, c3, CAP3, y2Th, b3, nullptr, mp3, nullptr, nullptr, y3Tf, y3Th);
    gather_keptT<<<NK * BB / 256, 256>>>(y3Tf, nzi + 3 * NK * CAP, nzv + 3 * NK * CAP, nzc + 3 * NK, kp);

    // 8) transpose y3 back to row-major for dense tail
    {
        dim3 blk(32, 8);
        transpose_h2h<<<dim3(BB / 32, PW / 32), blk>>>(y3Th, A3h, PW, BB);
    }

    // 9) layer 4/5 dense small GEMMs
    {
        dim3 g4(OUTD / BN, BB / BM);
        gemm_epi<0, true ><<<g4, 256, GEMM_SMEM>>>(A3h, W4h, A4, A4h, b4, BB, OUTD, PW);
        gemm_epi<0, false><<<g4, 256, GEMM_SMEM>>>(A4h, W5h, A5, nullptr, b5, BB, OUTD, OUTD);
    }

    // 10) fused head
    final_head<<<BB / 16, 256>>>(A5, kg, ki, kc, kp, clinn, W6, W7, out);
}